// round 14
// baseline (speedup 1.0000x reference)
#include <cuda_runtime.h>
#include <cuda_bf16.h>
#include <cstdint>
#include <math.h>

#define N_NODES 11201
#define E_PER_R 100000
#define N_REL   5
#define NNZ     (N_REL * E_PER_R)
#define NSEG    (N_REL * N_NODES)
#define D       512
#define KBIG    (N_REL * D)   // 2560
#define BATCH   32
#define FRAME   1200
#define M2PAD   1280
#define OUTW    1712
#define SCAN_NB 219           // ceil(56005/256)
#define NCHUNK  80            // KBIG/32
#define KSL     5             // gemm2 split-K slices (single wave)
#define CH_PER_SL (NCHUNK / KSL)  // 16

// ---------------- scratch (device globals; no allocation) ----------------
__device__ float g_x[N_NODES * D];
__device__ float g_h[N_NODES * D];
__device__ float g_emb[FRAME * D];
__device__ float g_y[(size_t)N_NODES * KBIG];          // tf32-rounded f32
__device__ __nv_bfloat16 g_y2hb[(size_t)M2PAD * KBIG]; // layer2 A hi
__device__ __nv_bfloat16 g_y2lb[(size_t)M2PAD * KBIG]; // layer2 A lo
__device__ float         g_w0h[(size_t)D * KBIG];      // W0^T tf32-rounded
__device__ __nv_bfloat16 g_w1hb[(size_t)D * KBIG];     // W1^T bf16 hi
__device__ __nv_bfloat16 g_w1lb[(size_t)D * KBIG];     // W1^T bf16 lo
__device__ float g_part[(size_t)KSL * M2PAD * D];

__device__ int   g_counts[NSEG];
__device__ int   g_rowptr[NSEG + 1];
__device__ int   g_cursor[NSEG];
__device__ int   g_bsum[256];
__device__ int   g_ccol[NNZ];
__device__ float g_cval[NNZ];

__device__ float g_c1[BATCH * 2048];
__device__ float g_c2[BATCH * D];
__device__ float g_c3[BATCH * D];
__device__ float g_q[BATCH * D];

__device__ __forceinline__ float* bufptr(int s) {
    switch (s) {
        case 1: return g_c1;
        case 2: return g_c2;
        case 3: return g_c3;
        case 4: return g_q;
        case 5: return g_emb;
    }
    return nullptr;
}

__device__ __forceinline__ uint32_t smem_u32(const void* p) {
    uint32_t a;
    asm("{ .reg .u64 t; cvta.to.shared.u64 t, %1; cvt.u32.u64 %0, t; }" : "=r"(a) : "l"(p));
    return a;
}
__device__ __forceinline__ float tf32r(float x) {
    float y;
    asm("cvt.rna.tf32.f32 %0, %1;" : "=f"(y) : "f"(x));
    return y;
}

// ---------------- init ----------------
__global__ void zero_k(float* out) {
    int i = blockIdx.x * 256 + threadIdx.x;   // grid 256 -> 65536 threads
    if (i < NSEG) g_counts[i] = 0;
    if (i < BATCH * 2048) g_c1[i] = 0.f;
    if (i < BATCH * D) { g_c2[i] = 0.f; g_c3[i] = 0.f; g_q[i] = 0.f; }
    if (i < BATCH * OUTW) out[i] = 0.f;
}

__global__ void build_x_k(const float* __restrict__ frame_emb,
                          const float* __restrict__ role_emb,
                          const int* __restrict__ fe_ids) {
    int row = blockIdx.x;
    int t = threadIdx.x; // 128
    const float4* src;
    if (row < FRAME) src = (const float4*)(frame_emb + (size_t)row * D);
    else             src = (const float4*)(role_emb + (size_t)fe_ids[row - FRAME] * D);
    ((float4*)(g_x + (size_t)row * D))[t] = src[t];
}

// W0[2560][512] -> WT[512][2560] tf32-rounded f32
__global__ void wtrans_f32_k(const float* __restrict__ W, float* __restrict__ WT) {
    __shared__ float t[32][33];
    int k0 = blockIdx.x * 32, n0 = blockIdx.y * 32;
    int tx = threadIdx.x, ty = threadIdx.y; // 32 x 8
#pragma unroll
    for (int i = ty; i < 32; i += 8)
        t[i][tx] = W[(size_t)(k0 + i) * D + n0 + tx];
    __syncthreads();
#pragma unroll
    for (int i = ty; i < 32; i += 8)
        WT[(size_t)(n0 + i) * KBIG + k0 + tx] = tf32r(t[tx][i]);
}

// W1[2560][512] -> WTh/WTl[512][2560] bf16 split
__global__ void wtrans_bf16_k(const float* __restrict__ W,
                              __nv_bfloat16* __restrict__ WTh,
                              __nv_bfloat16* __restrict__ WTl) {
    __shared__ float t[32][33];
    int k0 = blockIdx.x * 32, n0 = blockIdx.y * 32;
    int tx = threadIdx.x, ty = threadIdx.y;
#pragma unroll
    for (int i = ty; i < 32; i += 8)
        t[i][tx] = W[(size_t)(k0 + i) * D + n0 + tx];
    __syncthreads();
#pragma unroll
    for (int i = ty; i < 32; i += 8) {
        float v = t[tx][i];
        __nv_bfloat16 h = __float2bfloat16_rn(v);
        size_t o = (size_t)(n0 + i) * KBIG + k0 + tx;
        WTh[o] = h;
        WTl[o] = __float2bfloat16_rn(v - __bfloat162float(h));
    }
}

// ---------------- CSR build ----------------
__global__ void count_k(const int* __restrict__ rows) {
    int e = blockIdx.x * 256 + threadIdx.x;
    if (e < NNZ) {
        int r = e / E_PER_R;
        atomicAdd(&g_counts[r * N_NODES + rows[e]], 1);
    }
}

__global__ void scan1_k() {
    __shared__ int s[256];
    int i = blockIdx.x * 256 + threadIdx.x;
    int v = (i < NSEG) ? g_counts[i] : 0;
    s[threadIdx.x] = v;
    __syncthreads();
#pragma unroll
    for (int off = 1; off < 256; off <<= 1) {
        int a = (threadIdx.x >= off) ? s[threadIdx.x - off] : 0;
        __syncthreads();
        s[threadIdx.x] += a;
        __syncthreads();
    }
    if (i < NSEG) g_rowptr[i] = s[threadIdx.x] - v;
    if (threadIdx.x == 255) g_bsum[blockIdx.x] = s[255];
}

// merged scan2+scan3: every block redundantly scans the 219 block sums
__global__ void scan23_k() {
    __shared__ int s[256];
    int v = (threadIdx.x < SCAN_NB) ? g_bsum[threadIdx.x] : 0;
    s[threadIdx.x] = v;
    __syncthreads();
#pragma unroll
    for (int off = 1; off < 256; off <<= 1) {
        int a = (threadIdx.x >= off) ? s[threadIdx.x - off] : 0;
        __syncthreads();
        s[threadIdx.x] += a;
        __syncthreads();
    }
    int base = (blockIdx.x == 0) ? 0 : s[blockIdx.x - 1];  // exclusive prefix of bsums
    int i = blockIdx.x * 256 + threadIdx.x;
    if (i < NSEG) {
        int p = g_rowptr[i] + base;
        g_rowptr[i] = p;
        g_cursor[i] = p;
    }
    if (i == 0) g_rowptr[NSEG] = NNZ;
}

__global__ void scatter_k(const int* __restrict__ rows,
                          const int* __restrict__ cols,
                          const float* __restrict__ vals) {
    int e = blockIdx.x * 256 + threadIdx.x;
    if (e < NNZ) {
        int r = e / E_PER_R;
        int seg = r * N_NODES + rows[e];
        int pos = atomicAdd(&g_cursor[seg], 1);
        g_ccol[pos] = cols[e];
        g_cval[pos] = vals[e];
    }
}

// ---------------- segment gather core (4-edge ILP) ----------------
__device__ __forceinline__ float4 seg_gather(const float4* __restrict__ x4,
                                             int s, int e, int t) {
    float4 a0 = make_float4(0.f, 0.f, 0.f, 0.f);
    float4 a1 = make_float4(0.f, 0.f, 0.f, 0.f);
    float4 a2 = make_float4(0.f, 0.f, 0.f, 0.f);
    float4 a3 = make_float4(0.f, 0.f, 0.f, 0.f);
    int i = s;
    for (; i + 3 < e; i += 4) {
        int c0 = __ldg(&g_ccol[i]);
        int c1 = __ldg(&g_ccol[i + 1]);
        int c2 = __ldg(&g_ccol[i + 2]);
        int c3 = __ldg(&g_ccol[i + 3]);
        float v0 = __ldg(&g_cval[i]);
        float v1 = __ldg(&g_cval[i + 1]);
        float v2 = __ldg(&g_cval[i + 2]);
        float v3 = __ldg(&g_cval[i + 3]);
        float4 t0 = x4[(size_t)c0 * 128 + t];
        float4 t1 = x4[(size_t)c1 * 128 + t];
        float4 t2 = x4[(size_t)c2 * 128 + t];
        float4 t3 = x4[(size_t)c3 * 128 + t];
        a0.x += v0 * t0.x; a0.y += v0 * t0.y; a0.z += v0 * t0.z; a0.w += v0 * t0.w;
        a1.x += v1 * t1.x; a1.y += v1 * t1.y; a1.z += v1 * t1.z; a1.w += v1 * t1.w;
        a2.x += v2 * t2.x; a2.y += v2 * t2.y; a2.z += v2 * t2.z; a2.w += v2 * t2.w;
        a3.x += v3 * t3.x; a3.y += v3 * t3.y; a3.z += v3 * t3.z; a3.w += v3 * t3.w;
    }
    for (; i < e; ++i) {
        int c0 = __ldg(&g_ccol[i]);
        float v0 = __ldg(&g_cval[i]);
        float4 t0 = x4[(size_t)c0 * 128 + t];
        a0.x += v0 * t0.x; a0.y += v0 * t0.y; a0.z += v0 * t0.z; a0.w += v0 * t0.w;
    }
    a0.x += a1.x; a0.y += a1.y; a0.z += a1.z; a0.w += a1.w;
    a2.x += a3.x; a2.y += a3.y; a2.z += a3.z; a2.w += a3.w;
    a0.x += a2.x; a0.y += a2.y; a0.z += a2.z; a0.w += a2.w;
    return a0;
}

__global__ void __launch_bounds__(128) spmm1_k() {
    int seg = blockIdx.x;
    int r = seg / N_NODES;
    int row = seg - r * N_NODES;
    int t = threadIdx.x;
    float4 a = seg_gather((const float4*)g_x, g_rowptr[seg], g_rowptr[seg + 1], t);
    float4 o;
    o.x = tf32r(a.x); o.y = tf32r(a.y); o.z = tf32r(a.z); o.w = tf32r(a.w);
    *(float4*)(g_y + (size_t)row * KBIG + r * D + t * 4) = o;
}

__global__ void __launch_bounds__(128) spmm2_k() {
    int bid = blockIdx.x;               // 0 .. 5*FRAME-1
    int r = bid / FRAME;
    int row = bid - r * FRAME;
    int seg = r * N_NODES + row;
    int t = threadIdx.x;
    float4 a = seg_gather((const float4*)g_h, g_rowptr[seg], g_rowptr[seg + 1], t);
    size_t base = (size_t)row * KBIG + r * D + t * 4;
    float v[4] = { a.x, a.y, a.z, a.w };
    __nv_bfloat162 hb01, hb23, lb01, lb23;
    __nv_bfloat16 h0 = __float2bfloat16_rn(v[0]);
    __nv_bfloat16 h1 = __float2bfloat16_rn(v[1]);
    __nv_bfloat16 h2 = __float2bfloat16_rn(v[2]);
    __nv_bfloat16 h3 = __float2bfloat16_rn(v[3]);
    hb01.x = h0; hb01.y = h1; hb23.x = h2; hb23.y = h3;
    lb01.x = __float2bfloat16_rn(v[0] - __bfloat162float(h0));
    lb01.y = __float2bfloat16_rn(v[1] - __bfloat162float(h1));
    lb23.x = __float2bfloat16_rn(v[2] - __bfloat162float(h2));
    lb23.y = __float2bfloat16_rn(v[3] - __bfloat162float(h3));
    *(__nv_bfloat162*)(g_y2hb + base)     = hb01;
    *(__nv_bfloat162*)(g_y2hb + base + 2) = hb23;
    *(__nv_bfloat162*)(g_y2lb + base)     = lb01;
    *(__nv_bfloat162*)(g_y2lb + base + 2) = lb23;
}

// ---------------- MMA helpers ----------------
__device__ __forceinline__ void cp16(uint32_t dst, const void* src, uint32_t sz) {
    asm volatile("cp.async.cg.shared.global [%0], [%1], 16, %2;"
                 :: "r"(dst), "l"(src), "r"(sz));
}
__device__ __forceinline__ void mma_tf32(float* c, const uint32_t* a, const uint32_t* b) {
    asm volatile(
        "mma.sync.aligned.m16n8k8.row.col.f32.tf32.tf32.f32 "
        "{%0,%1,%2,%3}, {%4,%5,%6,%7}, {%8,%9}, {%0,%1,%2,%3};"
        : "+f"(c[0]), "+f"(c[1]), "+f"(c[2]), "+f"(c[3])
        : "r"(a[0]), "r"(a[1]), "r"(a[2]), "r"(a[3]), "r"(b[0]), "r"(b[1]));
}
__device__ __forceinline__ void mma_bf16(float* c, const uint32_t* a, const uint32_t* b) {
    asm volatile(
        "mma.sync.aligned.m16n8k16.row.col.f32.bf16.bf16.f32 "
        "{%0,%1,%2,%3}, {%4,%5,%6,%7}, {%8,%9}, {%0,%1,%2,%3};"
        : "+f"(c[0]), "+f"(c[1]), "+f"(c[2]), "+f"(c[3])
        : "r"(a[0]), "r"(a[1]), "r"(a[2]), "r"(a[3]), "r"(b[0]), "r"(b[1]));
}

// ========== GEMM1: g_h = tanh(g_y[M,2560] @ W0T^T), pure tf32 ==========
// R12-proven config: 64x128 tile, 4 warps, BK=32, 2-stage, 4 CTAs/SM, n-fast grid.
#define LF 36
#define A1_U32 (64 * LF)     // 2304
#define B1_U32 (128 * LF)    // 4608
#define S1_STAGE (A1_U32 + B1_U32)  // 6912 u32
#define G1_SMEM (2 * S1_STAGE * 4)  // 55296 B

__device__ __forceinline__ void g1_prefetch(uint32_t st, int kc, int m0, int n0, int tid) {
    int k0 = kc * 32;
#pragma unroll
    for (int i = 0; i < 4; ++i) {
        int idx = tid + i * 128;       // 0..511
        int row = idx >> 3, c4 = idx & 7;
        int m = m0 + row;
        bool ok = m < N_NODES;
        cp16(st + (uint32_t)(row * LF + c4 * 4) * 4,
             g_y + (size_t)(ok ? m : 0) * KBIG + k0 + c4 * 4, ok ? 16u : 0u);
    }
#pragma unroll
    for (int i = 0; i < 8; ++i) {
        int idx = tid + i * 128;       // 0..1023
        int row = idx >> 3, c4 = idx & 7;
        cp16(st + (uint32_t)(A1_U32 + row * LF + c4 * 4) * 4,
             g_w0h + (size_t)(n0 + row) * KBIG + k0 + c4 * 4, 16u);
    }
    asm volatile("cp.async.commit_group;" ::: "memory");
}

__global__ void __launch_bounds__(128, 4) gemm1_k() {
    extern __shared__ uint32_t sm[];
    int tid = threadIdx.x;
    int wid = tid >> 5, lane = tid & 31;
    int wm = wid & 1, wn = wid >> 1;
    int g = lane >> 2, t4 = lane & 3;
    int m0 = blockIdx.y * 64;            // m slow
    int n0 = blockIdx.x * 128;           // n fast
    uint32_t sb = smem_u32(sm);

    float acc[2][8][4];
#pragma unroll
    for (int mi = 0; mi < 2; ++mi)
#pragma unroll
        for (int ni = 0; ni < 8; ++ni)
#pragma unroll
            for (int j = 0; j < 4; ++j) acc[mi][ni][j] = 0.f;

    g1_prefetch(sb, 0, m0, n0, tid);

    for (int kc = 0; kc < NCHUNK; ++kc) {
        int b = kc & 1;
        if (kc + 1 < NCHUNK) {
            g1_prefetch(sb + (b ^ 1) * S1_STAGE * 4, kc + 1, m0, n0, tid);
            asm volatile("cp.async.wait_group 1;" ::: "memory");
        } else {
            asm volatile("cp.async.wait_group 0;" ::: "memory");
        }
        __syncthreads();

        const uint32_t* asu = sm + b * S1_STAGE;
        const uint32_t* bsu = asu + A1_U32;
#pragma unroll
        for (int ks = 0; ks < 4; ++ks) {
            int kk = ks * 8;
            uint32_t af[2][4], bf[8][2];
#pragma unroll
            for (int mi = 0; mi < 2; ++mi) {
                int r0 = wm * 32 + mi * 16 + g;
                af[mi][0] = asu[r0 * LF + kk + t4];
                af[mi][1] = asu[(r0 + 8) * LF + kk + t4];
                af[mi][2] = asu[r0 * LF + kk + t4 + 4];
                af[mi][3] = asu[(r0 + 8) * LF + kk + t4 + 4];
            }
#pragma unroll
            for (int ni = 0; ni < 8; ++ni) {
                int c0 = wn * 64 + ni * 8 + g;
                bf[ni][0] = bsu[c0 * LF + kk + t4];
                bf[ni][1] = bsu[c0 * LF + kk + t4 + 4];
            }
#pragma unroll
            for (int mi = 0; mi < 2; ++mi)
#pragma unroll
                for (int ni = 0; ni < 8; ++ni)
                    mma_tf32(acc[mi][ni], af[mi], bf[ni]);
        }
        __syncthreads();
    }

#pragma unroll
    for (int mi = 0; mi < 2; ++mi) {
        int row = m0 + wm * 32 + mi * 16 + g;
#pragma unroll
        for (int ni = 0; ni < 8; ++ni) {
            int col = n0 + wn * 64 + ni * 8 + 2 * t4;
            if (row < N_NODES) {
                float2 o = make_float2(tanhf(acc[mi][ni][0]), tanhf(acc[mi][ni][1]));
                *(float2*)(g_h + (size_t)row * D + col) = o;
            }
            if (row + 8 < N_NODES) {
                float2 o = make_float2(tanhf(acc[mi][ni][2]), tanhf(acc[mi][ni][3]));
                *(float2*)(g_h + (size_t)(row + 8) * D + col) = o;
            }
        }
    }
}

// ========== GEMM2: partials = y2 @ W1T^T, bf16x3, split-K(5), M=1280 ==========
#define LB 20
#define A2_U32 (64 * LB)     // 1280
#define B2_U32 (128 * LB)    // 2560
#define S2_AH 0
#define S2_AL A2_U32
#define S2_BH (2 * A2_U32)
#define S2_BL (2 * A2_U32 + B2_U32)
#define S2_STAGE (2 * A2_U32 + 2 * B2_U32)  // 7680 u32
#define G2_SMEM (2 * S2_STAGE * 4)          // 61440 B

__device__ __forceinline__ void g2_prefetch(uint32_t st, int kc, int m0, int n0, int tid) {
    int k0 = kc * 32;
#pragma unroll
    for (int i = 0; i < 2; ++i) {
        int idx = tid + i * 128;       // 0..255
        int row = idx >> 2, c4 = idx & 3;
        int m = m0 + row;
        bool ok = m < FRAME;
        size_t off = (size_t)(ok ? m : 0) * KBIG + k0 + c4 * 8;
        cp16(st + (uint32_t)(S2_AH + row * LB + c4 * 4) * 4, g_y2hb + off, ok ? 16u : 0u);
        cp16(st + (uint32_t)(S2_AL + row * LB + c4 * 4) * 4, g_y2lb + off, ok ? 16u : 0u);
    }
#pragma unroll
    for (int i = 0; i < 4; ++i) {
        int idx = tid + i * 128;       // 0..511
        int row = idx >> 2, c4 = idx & 3;
        size_t off = (size_t)(n0 + row) * KBIG + k0 + c4 * 8;
        cp16(st + (uint32_t)(S2_BH + row * LB + c4 * 4) * 4, g_w1hb + off, 16u);
        cp16(st + (uint32_t)(S2_BL + row * LB + c4 * 4) * 4, g_w1lb + off, 16u);
    }
    asm volatile("cp.async.commit_group;" ::: "memory");
}

__global__ void __launch_bounds__(128, 3) gemm2_k() {
    extern __shared__ uint32_t sm[];
    int tid = threadIdx.x;
    int wid = tid >> 5, lane = tid & 31;
    int wm = wid & 1, wn = wid >> 1;
    int g = lane >> 2, t4 = lane & 3;
    int m0 = blockIdx.x * 64;
    int n0 = blockIdx.y * 128;
    int z = blockIdx.z;
    int kc0 = z * CH_PER_SL;
    uint32_t sb = smem_u32(sm);

    float acc[2][8][4];
#pragma unroll
    for (int mi = 0; mi < 2; ++mi)
#pragma unroll
        for (int ni = 0; ni < 8; ++ni)
#pragma unroll
            for (int j = 0; j < 4; ++j) acc[mi][ni][j] = 0.f;

    g2_prefetch(sb, kc0, m0, n0, tid);

    for (int j = 0; j < CH_PER_SL; ++j) {
        int b = j & 1;
        if (j + 1 < CH_PER_SL) {
            g2_prefetch(sb + (b ^ 1) * S2_STAGE * 4, kc0 + j + 1, m0, n0, tid);
            asm volatile("cp.async.wait_group 1;" ::: "memory");
        } else {
            asm volatile("cp.async.wait_group 0;" ::: "memory");
        }
        __syncthreads();

        const uint32_t* base = sm + b * S2_STAGE;
        const uint32_t* ah = base + S2_AH;
        const uint32_t* al = base + S2_AL;
        const uint32_t* bh = base + S2_BH;
        const uint32_t* bl = base + S2_BL;
#pragma unroll
        for (int kh = 0; kh < 2; ++kh) {
            int ko = kh * 8;
            uint32_t ahf[2][4], alf[2][4], bhf[8][2], blf[8][2];
#pragma unroll
            for (int mi = 0; mi < 2; ++mi) {
                int r0 = wm * 32 + mi * 16 + g;
                int i0 = r0 * LB + ko + t4;
                int i1 = (r0 + 8) * LB + ko + t4;
                ahf[mi][0] = ah[i0];     ahf[mi][1] = ah[i1];
                ahf[mi][2] = ah[i0 + 4]; ahf[mi][3] = ah[i1 + 4];
                alf[mi][0] = al[i0];     alf[mi][1] = al[i1];
                alf[mi][2] = al[i0 + 4]; alf[mi][3] = al[i1 + 4];
            }
#pragma unroll
            for (int ni = 0; ni < 8; ++ni) {
                int c0 = wn * 64 + ni * 8 + g;
                int i0 = c0 * LB + ko + t4;
                bhf[ni][0] = bh[i0]; bhf[ni][1] = bh[i0 + 4];
                blf[ni][0] = bl[i0]; blf[ni][1] = bl[i0 + 4];
            }
#pragma unroll
            for (int mi = 0; mi < 2; ++mi)
#pragma unroll
                for (int ni = 0; ni < 8; ++ni) {
                    mma_bf16(acc[mi][ni], ahf[mi], bhf[ni]);
                    mma_bf16(acc[mi][ni], ahf[mi], blf[ni]);
                    mma_bf16(acc[mi][ni], alf[mi], bhf[ni]);
                }
        }
        __syncthreads();
    }

    float* out = g_part + (size_t)z * M2PAD * D;
#pragma unroll
    for (int mi = 0; mi < 2; ++mi) {
        int row = m0 + wm * 32 + mi * 16 + g;
#pragma unroll
        for (int ni = 0; ni < 8; ++ni) {
            int col = n0 + wn * 64 + ni * 8 + 2 * t4;
            *(float2*)(out + (size_t)row * D + col) =
                make_float2(acc[mi][ni][0], acc[mi][ni][1]);
            *(float2*)(out + (size_t)(row + 8) * D + col) =
                make_float2(acc[mi][ni][2], acc[mi][ni][3]);
        }
    }
}

__global__ void finalize_k() {
    int idx = blockIdx.x * 256 + threadIdx.x;
    if (idx >= FRAME * D) return;
    float s = 0.f;
#pragma unroll
    for (int z = 0; z < KSL; ++z)
        s += g_part[(size_t)z * M2PAD * D + idx];
    g_emb[idx] = tanhf(s);
}

// ---------------- small GEMM (M=32), split-K with atomic accumulate ----------------
template <bool BT>
__global__ void __launch_bounds__(256) sgemm_k(int asel, const float* Ain,
                                               int wsel, const float* Win,
                                               int csel, float* Cin,
                                               int K, int N, int ldc) {
    __shared__ float sA[32 * 33];
    __shared__ float sW[64 * 33];

    const float* __restrict__ A = (asel < 0) ? Ain : bufptr(asel);
    const float* __restrict__ W = (wsel < 0) ? Win : bufptr(wsel);
    float* __restrict__ C = (csel < 0) ? Cin : bufptr(csel);

    int tid = threadIdx.x;
    int tx = tid & 31;
    int ty = tid >> 5;
    int j0 = blockIdx.x * 64;
    int k0 = blockIdx.y * 256;

    float acc[4][2];
#pragma unroll
    for (int i = 0; i < 4; ++i) { acc[i][0] = 0.f; acc[i][1] = 0.f; }

    for (int kc = 0; kc < 256; kc += 32) {
        int kb = k0 + kc;
        for (int i = tid; i < 32 * 32; i += 256) {
            int kk = i & 31, bb = i >> 5;
            sA[kk * 33 + bb] = A[(size_t)bb * K + kb + kk];
        }
        if (!BT) {
            for (int i = tid; i < 64 * 32; i += 256) {
                int jl = i & 63, kk = i >> 6;
                int j = j0 + jl;
                sW[kk * 65 + jl] = (j < N) ? W[(size_t)(kb + kk) * N + j] : 0.f;
            }
        } else {
            for (int i = tid; i < 64 * 32; i += 256) {
                int kk = i & 31, jl = i >> 5;
                int j = j0 + jl;
                sW[jl * 33 + kk] = (j < N) ? W[(size_t)j * K + kb + kk] : 0.f;
            }
        }
        __syncthreads();
#pragma unroll 8
        for (int kk = 0; kk < 32; ++kk) {
            float w0 = BT ? sW[tx * 33 + kk] : sW[kk * 65 + tx];
            float w1 = BT ? sW[(tx + 32) * 33 + kk] : sW[kk * 65 + tx + 32];
#pragma unroll
            for (int i = 0; i < 4; ++i) {
                float a = sA[kk * 33 + ty + 8 * i];
                acc[i][0] += a * w0;
                acc[i][1] += a * w1;
            }
        }
        __syncthreads();
    }
#pragma unroll
    for (int i = 0; i < 4; ++i) {
        int b = ty + 8 * i;
        int j = j0 + tx;
        if (j < N) atomicAdd(&C[(size_t)b * ldc + j], acc[i][0]);
        j = j0 + tx + 32;
        if (j < N) atomicAdd(&C[(size_t)b * ldc + j], acc[i][1]);
    }
}

__global__ void bias_act_k(int csel, const float* __restrict__ bias, int N, int act) {
    int idx = blockIdx.x * 256 + threadIdx.x;
    if (idx >= BATCH * N) return;
    float* C = bufptr(csel);
    int j = idx % N;
    float v = C[idx] + bias[j];
    if (act == 1) v = fmaxf(v, 0.f);
    else if (act == 2) v = tanhf(v);
    C[idx] = v;
}

__global__ void fgather_k(const int* __restrict__ gold, const int* __restrict__ flist,
                          float* __restrict__ out) {
    int b = blockIdx.x;
    int t = threadIdx.x; // 128
    int label = flist[b * 16 + gold[b]];
    ((float4*)(out + (size_t)b * OUTW + FRAME))[t] =
        ((const float4*)(g_emb + (size_t)label * D))[t];
}

// ---------------- launcher (fork-join multi-stream graph) ----------------
extern "C" void kernel_launch(void* const* d_in, const int* in_sizes, int n_in,
                              void* d_out, int out_size) {
    const float* target_span = (const float*)d_in[0];
    const float* frame_emb   = (const float*)d_in[1];
    const float* role_emb    = (const float*)d_in[2];
    const float* rel_W0      = (const float*)d_in[3];
    const float* rel_W1      = (const float*)d_in[4];
    const float* span_W1     = (const float*)d_in[5];
    const float* span_b1     = (const float*)d_in[6];
    const float* span_W2     = (const float*)d_in[7];
    const float* span_b2     = (const float*)d_in[8];
    const float* fp_W1       = (const float*)d_in[9];
    const float* fp_b1       = (const float*)d_in[10];
    const float* fp_W2       = (const float*)d_in[11];
    const float* fp_b2       = (const float*)d_in[12];
    const float* adj_vals    = (const float*)d_in[13];
    const int*   fe_ids      = (const int*)d_in[14];
    const int*   adj_rows    = (const int*)d_in[15];
    const int*   adj_cols    = (const int*)d_in[16];
    const int*   gold        = (const int*)d_in[17];
    const int*   flist       = (const int*)d_in[18];
    float* out = (float*)d_out;

    static bool inited = false;
    static float *w0h;
    static __nv_bfloat16 *w1hb, *w1lb;
    static cudaStream_t s1, s2;
    static cudaEvent_t ev0, ev1, ev2;
    if (!inited) {
        cudaGetSymbolAddress((void**)&w0h, g_w0h);
        cudaGetSymbolAddress((void**)&w1hb, g_w1hb);
        cudaGetSymbolAddress((void**)&w1lb, g_w1lb);
        cudaFuncSetAttribute(gemm1_k, cudaFuncAttributeMaxDynamicSharedMemorySize, G1_SMEM);
        cudaFuncSetAttribute(gemm2_k, cudaFuncAttributeMaxDynamicSharedMemorySize, G2_SMEM);
        cudaStreamCreateWithFlags(&s1, cudaStreamNonBlocking);
        cudaStreamCreateWithFlags(&s2, cudaStreamNonBlocking);
        cudaEventCreateWithFlags(&ev0, cudaEventDisableTiming);
        cudaEventCreateWithFlags(&ev1, cudaEventDisableTiming);
        cudaEventCreateWithFlags(&ev2, cudaEventDisableTiming);
        inited = true;
    }

    // root: zeroing (counts + MLP accumulators + out)
    zero_k<<<256, 256>>>(out);
    cudaEventRecord(ev0, 0);
    cudaStreamWaitEvent(s1, ev0, 0);
    cudaStreamWaitEvent(s2, ev0, 0);

    // main branch: CSR build
    count_k<<<(NNZ + 255) / 256, 256>>>(adj_rows);
    scan1_k<<<SCAN_NB, 256>>>();
    scan23_k<<<SCAN_NB, 256>>>();
    scatter_k<<<(NNZ + 255) / 256, 256>>>(adj_rows, adj_cols, adj_vals);

    // branch s1: input assembly + weight transforms
    build_x_k<<<N_NODES, 128, 0, s1>>>(frame_emb, role_emb, fe_ids);
    wtrans_f32_k<<<dim3(KBIG / 32, D / 32), dim3(32, 8), 0, s1>>>(rel_W0, w0h);
    wtrans_bf16_k<<<dim3(KBIG / 32, D / 32), dim3(32, 8), 0, s1>>>(rel_W1, w1hb, w1lb);
    cudaEventRecord(ev1, s1);

    // branch s2: small MLP chain (only needed by the final einsum)
    sgemm_k<false><<<dim3(2048 / 64, 2048 / 256), 256, 0, s2>>>(-1, target_span, -1, span_W1, 1, nullptr, 2048, 2048, 2048);
    bias_act_k<<<(BATCH * 2048 + 255) / 256, 256, 0, s2>>>(1, span_b1, 2048, 1);
    sgemm_k<false><<<dim3(D / 64, 2048 / 256), 256, 0, s2>>>(1, nullptr, -1, span_W2, 2, nullptr, 2048, D, D);
    bias_act_k<<<(BATCH * D + 255) / 256, 256, 0, s2>>>(2, span_b2, D, 0);
    sgemm_k<false><<<dim3(D / 64, D / 256), 256, 0, s2>>>(2, nullptr, -1, fp_W1, 3, nullptr, D, D, D);
    bias_act_k<<<(BATCH * D + 255) / 256, 256, 0, s2>>>(3, fp_b1, D, 1);
    sgemm_k<false><<<dim3(D / 64, D / 256), 256, 0, s2>>>(3, nullptr, -1, fp_W2, 4, nullptr, D, D, D);
    bias_act_k<<<(BATCH * D + 255) / 256, 256, 0, s2>>>(4, fp_b2, D, 2);
    cudaEventRecord(ev2, s2);

    // join s1 before the GNN pipeline
    cudaStreamWaitEvent(0, ev1, 0);

    // Layer 1 (full M, pure tf32, R12 config)
    spmm1_k<<<NSEG, 128>>>();
    gemm1_k<<<dim3(D / 128, (N_NODES + 63) / 64), 128, G1_SMEM>>>();
    // Layer 2 (M truncated to FRAME, bf16x3 fully corrected, split-K=5)
    spmm2_k<<<N_REL * FRAME, 128>>>();
    gemm2_k<<<dim3(M2PAD / 64, D / 128, KSL), 128, G2_SMEM>>>();
    finalize_k<<<(FRAME * D + 255) / 256, 256>>>();

    // join s2, then einsum + gather
    cudaStreamWaitEvent(0, ev2, 0);
    sgemm_k<true><<<dim3((FRAME + 63) / 64, D / 256), 256>>>(4, nullptr, 5, nullptr, -1, out, D, FRAME, OUTW);
    fgather_k<<<BATCH, 128>>>(gold, flist, out);
}

// round 15
// speedup vs baseline: 1.0391x; 1.0391x over previous
#include <cuda_runtime.h>
#include <cuda_bf16.h>
#include <cstdint>
#include <math.h>

#define N_NODES 11201
#define E_PER_R 100000
#define N_REL   5
#define NNZ     (N_REL * E_PER_R)
#define NSEG    (N_REL * N_NODES)
#define D       512
#define KBIG    (N_REL * D)   // 2560
#define BATCH   32
#define FRAME   1200
#define M2PAD   1280
#define OUTW    1712
#define SCAN_NB 219           // ceil(56005/256)
#define NCHUNK  80            // KBIG/32
#define KSL     5             // gemm2 split-K slices (single wave)
#define CH_PER_SL (NCHUNK / KSL)  // 16

// ---------------- scratch (device globals; no allocation) ----------------
__device__ float g_x[N_NODES * D];
__device__ float g_h[N_NODES * D];
__device__ float g_emb[FRAME * D];
__device__ float g_y[(size_t)N_NODES * KBIG];          // tf32-rounded f32
__device__ __nv_bfloat16 g_y2hb[(size_t)M2PAD * KBIG]; // layer2 A hi
__device__ __nv_bfloat16 g_y2lb[(size_t)M2PAD * KBIG]; // layer2 A lo
__device__ float         g_w0h[(size_t)D * KBIG];      // W0^T tf32-rounded
__device__ __nv_bfloat16 g_w1hb[(size_t)D * KBIG];     // W1^T bf16 hi
__device__ __nv_bfloat16 g_w1lb[(size_t)D * KBIG];     // W1^T bf16 lo
__device__ float g_part[(size_t)KSL * M2PAD * D];

__device__ int   g_counts[NSEG];
__device__ int   g_rowptr[NSEG + 1];
__device__ int   g_cursor[NSEG];
__device__ int   g_bsum[256];
__device__ int   g_ccol[NNZ];
__device__ float g_cval[NNZ];

__device__ float g_c1[BATCH * 2048];
__device__ float g_c2[BATCH * D];
__device__ float g_c3[BATCH * D];
__device__ float g_q[BATCH * D];

__device__ __forceinline__ float* bufptr(int s) {
    switch (s) {
        case 1: return g_c1;
        case 2: return g_c2;
        case 3: return g_c3;
        case 4: return g_q;
        case 5: return g_emb;
    }
    return nullptr;
}

__device__ __forceinline__ uint32_t smem_u32(const void* p) {
    uint32_t a;
    asm("{ .reg .u64 t; cvta.to.shared.u64 t, %1; cvt.u32.u64 %0, t; }" : "=r"(a) : "l"(p));
    return a;
}
__device__ __forceinline__ float tf32r(float x) {
    float y;
    asm("cvt.rna.tf32.f32 %0, %1;" : "=f"(y) : "f"(x));
    return y;
}

// ---------------- init ----------------
__global__ void zero_k(float* out) {
    int i = blockIdx.x * 256 + threadIdx.x;   // grid 256 -> 65536 threads
    if (i < NSEG) g_counts[i] = 0;
    if (i < BATCH * 2048) g_c1[i] = 0.f;
    if (i < BATCH * D) { g_c2[i] = 0.f; g_c3[i] = 0.f; g_q[i] = 0.f; }
    if (i < BATCH * OUTW) out[i] = 0.f;
}

__global__ void build_x_k(const float* __restrict__ frame_emb,
                          const float* __restrict__ role_emb,
                          const int* __restrict__ fe_ids) {
    int row = blockIdx.x;
    int t = threadIdx.x; // 128
    const float4* src;
    if (row < FRAME) src = (const float4*)(frame_emb + (size_t)row * D);
    else             src = (const float4*)(role_emb + (size_t)fe_ids[row - FRAME] * D);
    ((float4*)(g_x + (size_t)row * D))[t] = src[t];
}

// W0[2560][512] -> WT[512][2560] tf32-rounded f32
__global__ void wtrans_f32_k(const float* __restrict__ W, float* __restrict__ WT) {
    __shared__ float t[32][33];
    int k0 = blockIdx.x * 32, n0 = blockIdx.y * 32;
    int tx = threadIdx.x, ty = threadIdx.y; // 32 x 8
#pragma unroll
    for (int i = ty; i < 32; i += 8)
        t[i][tx] = W[(size_t)(k0 + i) * D + n0 + tx];
    __syncthreads();
#pragma unroll
    for (int i = ty; i < 32; i += 8)
        WT[(size_t)(n0 + i) * KBIG + k0 + tx] = tf32r(t[tx][i]);
}

// W1[2560][512] -> WTh/WTl[512][2560] bf16 split
__global__ void wtrans_bf16_k(const float* __restrict__ W,
                              __nv_bfloat16* __restrict__ WTh,
                              __nv_bfloat16* __restrict__ WTl) {
    __shared__ float t[32][33];
    int k0 = blockIdx.x * 32, n0 = blockIdx.y * 32;
    int tx = threadIdx.x, ty = threadIdx.y;
#pragma unroll
    for (int i = ty; i < 32; i += 8)
        t[i][tx] = W[(size_t)(k0 + i) * D + n0 + tx];
    __syncthreads();
#pragma unroll
    for (int i = ty; i < 32; i += 8) {
        float v = t[tx][i];
        __nv_bfloat16 h = __float2bfloat16_rn(v);
        size_t o = (size_t)(n0 + i) * KBIG + k0 + tx;
        WTh[o] = h;
        WTl[o] = __float2bfloat16_rn(v - __bfloat162float(h));
    }
}

// ---------------- CSR build ----------------
__global__ void count_k(const int* __restrict__ rows) {
    int e = blockIdx.x * 256 + threadIdx.x;
    if (e < NNZ) {
        int r = e / E_PER_R;
        atomicAdd(&g_counts[r * N_NODES + rows[e]], 1);
    }
}

__global__ void scan1_k() {
    __shared__ int s[256];
    int i = blockIdx.x * 256 + threadIdx.x;
    int v = (i < NSEG) ? g_counts[i] : 0;
    s[threadIdx.x] = v;
    __syncthreads();
#pragma unroll
    for (int off = 1; off < 256; off <<= 1) {
        int a = (threadIdx.x >= off) ? s[threadIdx.x - off] : 0;
        __syncthreads();
        s[threadIdx.x] += a;
        __syncthreads();
    }
    if (i < NSEG) g_rowptr[i] = s[threadIdx.x] - v;
    if (threadIdx.x == 255) g_bsum[blockIdx.x] = s[255];
}

// merged scan2+scan3: every block redundantly scans the 219 block sums
__global__ void scan23_k() {
    __shared__ int s[256];
    int v = (threadIdx.x < SCAN_NB) ? g_bsum[threadIdx.x] : 0;
    s[threadIdx.x] = v;
    __syncthreads();
#pragma unroll
    for (int off = 1; off < 256; off <<= 1) {
        int a = (threadIdx.x >= off) ? s[threadIdx.x - off] : 0;
        __syncthreads();
        s[threadIdx.x] += a;
        __syncthreads();
    }
    int base = (blockIdx.x == 0) ? 0 : s[blockIdx.x - 1];  // exclusive prefix of bsums
    int i = blockIdx.x * 256 + threadIdx.x;
    if (i < NSEG) {
        int p = g_rowptr[i] + base;
        g_rowptr[i] = p;
        g_cursor[i] = p;
    }
    if (i == 0) g_rowptr[NSEG] = NNZ;
}

__global__ void scatter_k(const int* __restrict__ rows,
                          const int* __restrict__ cols,
                          const float* __restrict__ vals) {
    int e = blockIdx.x * 256 + threadIdx.x;
    if (e < NNZ) {
        int r = e / E_PER_R;
        int seg = r * N_NODES + rows[e];
        int pos = atomicAdd(&g_cursor[seg], 1);
        g_ccol[pos] = cols[e];
        g_cval[pos] = vals[e];
    }
}

// ---------------- segment gather core (2-edge ILP, proven optimal) ----------------
__device__ __forceinline__ float4 seg_gather(const float4* __restrict__ x4,
                                             int s, int e, int t) {
    float4 acc0 = make_float4(0.f, 0.f, 0.f, 0.f);
    float4 acc1 = make_float4(0.f, 0.f, 0.f, 0.f);
    int i = s;
    for (; i + 1 < e; i += 2) {
        int c0 = __ldg(&g_ccol[i]);
        int c1 = __ldg(&g_ccol[i + 1]);
        float v0 = __ldg(&g_cval[i]);
        float v1 = __ldg(&g_cval[i + 1]);
        float4 t0 = x4[(size_t)c0 * 128 + t];
        float4 t1 = x4[(size_t)c1 * 128 + t];
        acc0.x += v0 * t0.x; acc0.y += v0 * t0.y; acc0.z += v0 * t0.z; acc0.w += v0 * t0.w;
        acc1.x += v1 * t1.x; acc1.y += v1 * t1.y; acc1.z += v1 * t1.z; acc1.w += v1 * t1.w;
    }
    if (i < e) {
        int c0 = __ldg(&g_ccol[i]);
        float v0 = __ldg(&g_cval[i]);
        float4 t0 = x4[(size_t)c0 * 128 + t];
        acc0.x += v0 * t0.x; acc0.y += v0 * t0.y; acc0.z += v0 * t0.z; acc0.w += v0 * t0.w;
    }
    acc0.x += acc1.x; acc0.y += acc1.y; acc0.z += acc1.z; acc0.w += acc1.w;
    return acc0;
}

__global__ void __launch_bounds__(128) spmm1_k() {
    int seg = blockIdx.x;
    int r = seg / N_NODES;
    int row = seg - r * N_NODES;
    int t = threadIdx.x;
    float4 a = seg_gather((const float4*)g_x, g_rowptr[seg], g_rowptr[seg + 1], t);
    float4 o;
    o.x = tf32r(a.x); o.y = tf32r(a.y); o.z = tf32r(a.z); o.w = tf32r(a.w);
    *(float4*)(g_y + (size_t)row * KBIG + r * D + t * 4) = o;
}

__global__ void __launch_bounds__(128) spmm2_k() {
    int bid = blockIdx.x;               // 0 .. 5*FRAME-1
    int r = bid / FRAME;
    int row = bid - r * FRAME;
    int seg = r * N_NODES + row;
    int t = threadIdx.x;
    float4 a = seg_gather((const float4*)g_h, g_rowptr[seg], g_rowptr[seg + 1], t);
    size_t base = (size_t)row * KBIG + r * D + t * 4;
    float v[4] = { a.x, a.y, a.z, a.w };
    __nv_bfloat162 hb01, hb23, lb01, lb23;
    __nv_bfloat16 h0 = __float2bfloat16_rn(v[0]);
    __nv_bfloat16 h1 = __float2bfloat16_rn(v[1]);
    __nv_bfloat16 h2 = __float2bfloat16_rn(v[2]);
    __nv_bfloat16 h3 = __float2bfloat16_rn(v[3]);
    hb01.x = h0; hb01.y = h1; hb23.x = h2; hb23.y = h3;
    lb01.x = __float2bfloat16_rn(v[0] - __bfloat162float(h0));
    lb01.y = __float2bfloat16_rn(v[1] - __bfloat162float(h1));
    lb23.x = __float2bfloat16_rn(v[2] - __bfloat162float(h2));
    lb23.y = __float2bfloat16_rn(v[3] - __bfloat162float(h3));
    *(__nv_bfloat162*)(g_y2hb + base)     = hb01;
    *(__nv_bfloat162*)(g_y2hb + base + 2) = hb23;
    *(__nv_bfloat162*)(g_y2lb + base)     = lb01;
    *(__nv_bfloat162*)(g_y2lb + base + 2) = lb23;
}

// ---------------- MMA helpers ----------------
__device__ __forceinline__ void cp16(uint32_t dst, const void* src, uint32_t sz) {
    asm volatile("cp.async.cg.shared.global [%0], [%1], 16, %2;"
                 :: "r"(dst), "l"(src), "r"(sz));
}
__device__ __forceinline__ void mma_tf32(float* c, const uint32_t* a, const uint32_t* b) {
    asm volatile(
        "mma.sync.aligned.m16n8k8.row.col.f32.tf32.tf32.f32 "
        "{%0,%1,%2,%3}, {%4,%5,%6,%7}, {%8,%9}, {%0,%1,%2,%3};"
        : "+f"(c[0]), "+f"(c[1]), "+f"(c[2]), "+f"(c[3])
        : "r"(a[0]), "r"(a[1]), "r"(a[2]), "r"(a[3]), "r"(b[0]), "r"(b[1]));
}
__device__ __forceinline__ void mma_bf16(float* c, const uint32_t* a, const uint32_t* b) {
    asm volatile(
        "mma.sync.aligned.m16n8k16.row.col.f32.bf16.bf16.f32 "
        "{%0,%1,%2,%3}, {%4,%5,%6,%7}, {%8,%9}, {%0,%1,%2,%3};"
        : "+f"(c[0]), "+f"(c[1]), "+f"(c[2]), "+f"(c[3])
        : "r"(a[0]), "r"(a[1]), "r"(a[2]), "r"(a[3]), "r"(b[0]), "r"(b[1]));
}

// ========== GEMM1: g_h = tanh(g_y[M,2560] @ W0T^T), pure tf32 ==========
// Champion config: 64x128 tile, 4 warps, BK=32, 2-stage, 4 CTAs/SM, n-fast grid.
#define LF 36
#define A1_U32 (64 * LF)     // 2304
#define B1_U32 (128 * LF)    // 4608
#define S1_STAGE (A1_U32 + B1_U32)  // 6912 u32
#define G1_SMEM (2 * S1_STAGE * 4)  // 55296 B

__device__ __forceinline__ void g1_prefetch(uint32_t st, int kc, int m0, int n0, int tid) {
    int k0 = kc * 32;
#pragma unroll
    for (int i = 0; i < 4; ++i) {
        int idx = tid + i * 128;       // 0..511
        int row = idx >> 3, c4 = idx & 7;
        int m = m0 + row;
        bool ok = m < N_NODES;
        cp16(st + (uint32_t)(row * LF + c4 * 4) * 4,
             g_y + (size_t)(ok ? m : 0) * KBIG + k0 + c4 * 4, ok ? 16u : 0u);
    }
#pragma unroll
    for (int i = 0; i < 8; ++i) {
        int idx = tid + i * 128;       // 0..1023
        int row = idx >> 3, c4 = idx & 7;
        cp16(st + (uint32_t)(A1_U32 + row * LF + c4 * 4) * 4,
             g_w0h + (size_t)(n0 + row) * KBIG + k0 + c4 * 4, 16u);
    }
    asm volatile("cp.async.commit_group;" ::: "memory");
}

__global__ void __launch_bounds__(128, 4) gemm1_k() {
    extern __shared__ uint32_t sm[];
    int tid = threadIdx.x;
    int wid = tid >> 5, lane = tid & 31;
    int wm = wid & 1, wn = wid >> 1;
    int g = lane >> 2, t4 = lane & 3;
    int m0 = blockIdx.y * 64;            // m slow
    int n0 = blockIdx.x * 128;           // n fast
    uint32_t sb = smem_u32(sm);

    float acc[2][8][4];
#pragma unroll
    for (int mi = 0; mi < 2; ++mi)
#pragma unroll
        for (int ni = 0; ni < 8; ++ni)
#pragma unroll
            for (int j = 0; j < 4; ++j) acc[mi][ni][j] = 0.f;

    g1_prefetch(sb, 0, m0, n0, tid);

    for (int kc = 0; kc < NCHUNK; ++kc) {
        int b = kc & 1;
        if (kc + 1 < NCHUNK) {
            g1_prefetch(sb + (b ^ 1) * S1_STAGE * 4, kc + 1, m0, n0, tid);
            asm volatile("cp.async.wait_group 1;" ::: "memory");
        } else {
            asm volatile("cp.async.wait_group 0;" ::: "memory");
        }
        __syncthreads();

        const uint32_t* asu = sm + b * S1_STAGE;
        const uint32_t* bsu = asu + A1_U32;
#pragma unroll
        for (int ks = 0; ks < 4; ++ks) {
            int kk = ks * 8;
            uint32_t af[2][4], bf[8][2];
#pragma unroll
            for (int mi = 0; mi < 2; ++mi) {
                int r0 = wm * 32 + mi * 16 + g;
                af[mi][0] = asu[r0 * LF + kk + t4];
                af[mi][1] = asu[(r0 + 8) * LF + kk + t4];
                af[mi][2] = asu[r0 * LF + kk + t4 + 4];
                af[mi][3] = asu[(r0 + 8) * LF + kk + t4 + 4];
            }
#pragma unroll
            for (int ni = 0; ni < 8; ++ni) {
                int c0 = wn * 64 + ni * 8 + g;
                bf[ni][0] = bsu[c0 * LF + kk + t4];
                bf[ni][1] = bsu[c0 * LF + kk + t4 + 4];
            }
#pragma unroll
            for (int mi = 0; mi < 2; ++mi)
#pragma unroll
                for (int ni = 0; ni < 8; ++ni)
                    mma_tf32(acc[mi][ni], af[mi], bf[ni]);
        }
        __syncthreads();
    }

#pragma unroll
    for (int mi = 0; mi < 2; ++mi) {
        int row = m0 + wm * 32 + mi * 16 + g;
#pragma unroll
        for (int ni = 0; ni < 8; ++ni) {
            int col = n0 + wn * 64 + ni * 8 + 2 * t4;
            if (row < N_NODES) {
                float2 o = make_float2(tanhf(acc[mi][ni][0]), tanhf(acc[mi][ni][1]));
                *(float2*)(g_h + (size_t)row * D + col) = o;
            }
            if (row + 8 < N_NODES) {
                float2 o = make_float2(tanhf(acc[mi][ni][2]), tanhf(acc[mi][ni][3]));
                *(float2*)(g_h + (size_t)(row + 8) * D + col) = o;
            }
        }
    }
}

// ========== GEMM2: partials = y2 @ W1T^T, bf16x3, split-K(5), M=1280 ==========
#define LB 20
#define A2_U32 (64 * LB)     // 1280
#define B2_U32 (128 * LB)    // 2560
#define S2_AH 0
#define S2_AL A2_U32
#define S2_BH (2 * A2_U32)
#define S2_BL (2 * A2_U32 + B2_U32)
#define S2_STAGE (2 * A2_U32 + 2 * B2_U32)  // 7680 u32
#define G2_SMEM (2 * S2_STAGE * 4)          // 61440 B

__device__ __forceinline__ void g2_prefetch(uint32_t st, int kc, int m0, int n0, int tid) {
    int k0 = kc * 32;
#pragma unroll
    for (int i = 0; i < 2; ++i) {
        int idx = tid + i * 128;       // 0..255
        int row = idx >> 2, c4 = idx & 3;
        int m = m0 + row;
        bool ok = m < FRAME;
        size_t off = (size_t)(ok ? m : 0) * KBIG + k0 + c4 * 8;
        cp16(st + (uint32_t)(S2_AH + row * LB + c4 * 4) * 4, g_y2hb + off, ok ? 16u : 0u);
        cp16(st + (uint32_t)(S2_AL + row * LB + c4 * 4) * 4, g_y2lb + off, ok ? 16u : 0u);
    }
#pragma unroll
    for (int i = 0; i < 4; ++i) {
        int idx = tid + i * 128;       // 0..511
        int row = idx >> 2, c4 = idx & 3;
        size_t off = (size_t)(n0 + row) * KBIG + k0 + c4 * 8;
        cp16(st + (uint32_t)(S2_BH + row * LB + c4 * 4) * 4, g_w1hb + off, 16u);
        cp16(st + (uint32_t)(S2_BL + row * LB + c4 * 4) * 4, g_w1lb + off, 16u);
    }
    asm volatile("cp.async.commit_group;" ::: "memory");
}

__global__ void __launch_bounds__(128, 3) gemm2_k() {
    extern __shared__ uint32_t sm[];
    int tid = threadIdx.x;
    int wid = tid >> 5, lane = tid & 31;
    int wm = wid & 1, wn = wid >> 1;
    int g = lane >> 2, t4 = lane & 3;
    int m0 = blockIdx.x * 64;
    int n0 = blockIdx.y * 128;
    int z = blockIdx.z;
    int kc0 = z * CH_PER_SL;
    uint32_t sb = smem_u32(sm);

    float acc[2][8][4];
#pragma unroll
    for (int mi = 0; mi < 2; ++mi)
#pragma unroll
        for (int ni = 0; ni < 8; ++ni)
#pragma unroll
            for (int j = 0; j < 4; ++j) acc[mi][ni][j] = 0.f;

    g2_prefetch(sb, kc0, m0, n0, tid);

    for (int j = 0; j < CH_PER_SL; ++j) {
        int b = j & 1;
        if (j + 1 < CH_PER_SL) {
            g2_prefetch(sb + (b ^ 1) * S2_STAGE * 4, kc0 + j + 1, m0, n0, tid);
            asm volatile("cp.async.wait_group 1;" ::: "memory");
        } else {
            asm volatile("cp.async.wait_group 0;" ::: "memory");
        }
        __syncthreads();

        const uint32_t* base = sm + b * S2_STAGE;
        const uint32_t* ah = base + S2_AH;
        const uint32_t* al = base + S2_AL;
        const uint32_t* bh = base + S2_BH;
        const uint32_t* bl = base + S2_BL;
#pragma unroll
        for (int kh = 0; kh < 2; ++kh) {
            int ko = kh * 8;
            uint32_t ahf[2][4], alf[2][4], bhf[8][2], blf[8][2];
#pragma unroll
            for (int mi = 0; mi < 2; ++mi) {
                int r0 = wm * 32 + mi * 16 + g;
                int i0 = r0 * LB + ko + t4;
                int i1 = (r0 + 8) * LB + ko + t4;
                ahf[mi][0] = ah[i0];     ahf[mi][1] = ah[i1];
                ahf[mi][2] = ah[i0 + 4]; ahf[mi][3] = ah[i1 + 4];
                alf[mi][0] = al[i0];     alf[mi][1] = al[i1];
                alf[mi][2] = al[i0 + 4]; alf[mi][3] = al[i1 + 4];
            }
#pragma unroll
            for (int ni = 0; ni < 8; ++ni) {
                int c0 = wn * 64 + ni * 8 + g;
                int i0 = c0 * LB + ko + t4;
                bhf[ni][0] = bh[i0]; bhf[ni][1] = bh[i0 + 4];
                blf[ni][0] = bl[i0]; blf[ni][1] = bl[i0 + 4];
            }
#pragma unroll
            for (int mi = 0; mi < 2; ++mi)
#pragma unroll
                for (int ni = 0; ni < 8; ++ni) {
                    mma_bf16(acc[mi][ni], ahf[mi], bhf[ni]);
                    mma_bf16(acc[mi][ni], ahf[mi], blf[ni]);
                    mma_bf16(acc[mi][ni], alf[mi], bhf[ni]);
                }
        }
        __syncthreads();
    }

    float* out = g_part + (size_t)z * M2PAD * D;
#pragma unroll
    for (int mi = 0; mi < 2; ++mi) {
        int row = m0 + wm * 32 + mi * 16 + g;
#pragma unroll
        for (int ni = 0; ni < 8; ++ni) {
            int col = n0 + wn * 64 + ni * 8 + 2 * t4;
            *(float2*)(out + (size_t)row * D + col) =
                make_float2(acc[mi][ni][0], acc[mi][ni][1]);
            *(float2*)(out + (size_t)(row + 8) * D + col) =
                make_float2(acc[mi][ni][2], acc[mi][ni][3]);
        }
    }
}

__global__ void finalize_k() {
    int idx = blockIdx.x * 256 + threadIdx.x;
    if (idx >= FRAME * D) return;
    float s = 0.f;
#pragma unroll
    for (int z = 0; z < KSL; ++z)
        s += g_part[(size_t)z * M2PAD * D + idx];
    g_emb[idx] = tanhf(s);
}

// ---------------- small GEMM (M=32), split-K with atomic accumulate ----------------
template <bool BT>
__global__ void __launch_bounds__(256) sgemm_k(int asel, const float* Ain,
                                               int wsel, const float* Win,
                                               int csel, float* Cin,
                                               int K, int N, int ldc) {
    __shared__ float sA[32 * 33];
    __shared__ float sW[64 * 33];

    const float* __restrict__ A = (asel < 0) ? Ain : bufptr(asel);
    const float* __restrict__ W = (wsel < 0) ? Win : bufptr(wsel);
    float* __restrict__ C = (csel < 0) ? Cin : bufptr(csel);

    int tid = threadIdx.x;
    int tx = tid & 31;
    int ty = tid >> 5;
    int j0 = blockIdx.x * 64;
    int k0 = blockIdx.y * 256;

    float acc[4][2];
#pragma unroll
    for (int i = 0; i < 4; ++i) { acc[i][0] = 0.f; acc[i][1] = 0.f; }

    for (int kc = 0; kc < 256; kc += 32) {
        int kb = k0 + kc;
        for (int i = tid; i < 32 * 32; i += 256) {
            int kk = i & 31, bb = i >> 5;
            sA[kk * 33 + bb] = A[(size_t)bb * K + kb + kk];
        }
        if (!BT) {
            for (int i = tid; i < 64 * 32; i += 256) {
                int jl = i & 63, kk = i >> 6;
                int j = j0 + jl;
                sW[kk * 65 + jl] = (j < N) ? W[(size_t)(kb + kk) * N + j] : 0.f;
            }
        } else {
            for (int i = tid; i < 64 * 32; i += 256) {
                int kk = i & 31, jl = i >> 5;
                int j = j0 + jl;
                sW[jl * 33 + kk] = (j < N) ? W[(size_t)j * K + kb + kk] : 0.f;
            }
        }
        __syncthreads();
#pragma unroll 8
        for (int kk = 0; kk < 32; ++kk) {
            float w0 = BT ? sW[tx * 33 + kk] : sW[kk * 65 + tx];
            float w1 = BT ? sW[(tx + 32) * 33 + kk] : sW[kk * 65 + tx + 32];
#pragma unroll
            for (int i = 0; i < 4; ++i) {
                float a = sA[kk * 33 + ty + 8 * i];
                acc[i][0] += a * w0;
                acc[i][1] += a * w1;
            }
        }
        __syncthreads();
    }
#pragma unroll
    for (int i = 0; i < 4; ++i) {
        int b = ty + 8 * i;
        int j = j0 + tx;
        if (j < N) atomicAdd(&C[(size_t)b * ldc + j], acc[i][0]);
        j = j0 + tx + 32;
        if (j < N) atomicAdd(&C[(size_t)b * ldc + j], acc[i][1]);
    }
}

__global__ void bias_act_k(int csel, const float* __restrict__ bias, int N, int act) {
    int idx = blockIdx.x * 256 + threadIdx.x;
    if (idx >= BATCH * N) return;
    float* C = bufptr(csel);
    int j = idx % N;
    float v = C[idx] + bias[j];
    if (act == 1) v = fmaxf(v, 0.f);
    else if (act == 2) v = tanhf(v);
    C[idx] = v;
}

__global__ void fgather_k(const int* __restrict__ gold, const int* __restrict__ flist,
                          float* __restrict__ out) {
    int b = blockIdx.x;
    int t = threadIdx.x; // 128
    int label = flist[b * 16 + gold[b]];
    ((float4*)(out + (size_t)b * OUTW + FRAME))[t] =
        ((const float4*)(g_emb + (size_t)label * D))[t];
}

// ---------------- launcher (fork-join multi-stream graph) ----------------
extern "C" void kernel_launch(void* const* d_in, const int* in_sizes, int n_in,
                              void* d_out, int out_size) {
    const float* target_span = (const float*)d_in[0];
    const float* frame_emb   = (const float*)d_in[1];
    const float* role_emb    = (const float*)d_in[2];
    const float* rel_W0      = (const float*)d_in[3];
    const float* rel_W1      = (const float*)d_in[4];
    const float* span_W1     = (const float*)d_in[5];
    const float* span_b1     = (const float*)d_in[6];
    const float* span_W2     = (const float*)d_in[7];
    const float* span_b2     = (const float*)d_in[8];
    const float* fp_W1       = (const float*)d_in[9];
    const float* fp_b1       = (const float*)d_in[10];
    const float* fp_W2       = (const float*)d_in[11];
    const float* fp_b2       = (const float*)d_in[12];
    const float* adj_vals    = (const float*)d_in[13];
    const int*   fe_ids      = (const int*)d_in[14];
    const int*   adj_rows    = (const int*)d_in[15];
    const int*   adj_cols    = (const int*)d_in[16];
    const int*   gold        = (const int*)d_in[17];
    const int*   flist       = (const int*)d_in[18];
    float* out = (float*)d_out;

    static bool inited = false;
    static float *w0h;
    static __nv_bfloat16 *w1hb, *w1lb;
    static cudaStream_t s1, s2;
    static cudaEvent_t ev0, ev1, ev2;
    if (!inited) {
        cudaGetSymbolAddress((void**)&w0h, g_w0h);
        cudaGetSymbolAddress((void**)&w1hb, g_w1hb);
        cudaGetSymbolAddress((void**)&w1lb, g_w1lb);
        cudaFuncSetAttribute(gemm1_k, cudaFuncAttributeMaxDynamicSharedMemorySize, G1_SMEM);
        cudaFuncSetAttribute(gemm2_k, cudaFuncAttributeMaxDynamicSharedMemorySize, G2_SMEM);
        cudaStreamCreateWithFlags(&s1, cudaStreamNonBlocking);
        cudaStreamCreateWithFlags(&s2, cudaStreamNonBlocking);
        cudaEventCreateWithFlags(&ev0, cudaEventDisableTiming);
        cudaEventCreateWithFlags(&ev1, cudaEventDisableTiming);
        cudaEventCreateWithFlags(&ev2, cudaEventDisableTiming);
        inited = true;
    }

    // root: zeroing (counts + MLP accumulators + out)
    zero_k<<<256, 256>>>(out);
    cudaEventRecord(ev0, 0);
    cudaStreamWaitEvent(s1, ev0, 0);
    cudaStreamWaitEvent(s2, ev0, 0);

    // main branch: CSR build
    count_k<<<(NNZ + 255) / 256, 256>>>(adj_rows);
    scan1_k<<<SCAN_NB, 256>>>();
    scan23_k<<<SCAN_NB, 256>>>();
    scatter_k<<<(NNZ + 255) / 256, 256>>>(adj_rows, adj_cols, adj_vals);

    // branch s1: input assembly + weight transforms
    build_x_k<<<N_NODES, 128, 0, s1>>>(frame_emb, role_emb, fe_ids);
    wtrans_f32_k<<<dim3(KBIG / 32, D / 32), dim3(32, 8), 0, s1>>>(rel_W0, w0h);
    wtrans_bf16_k<<<dim3(KBIG / 32, D / 32), dim3(32, 8), 0, s1>>>(rel_W1, w1hb, w1lb);
    cudaEventRecord(ev1, s1);

    // branch s2: small MLP chain (only needed by the final einsum)
    sgemm_k<false><<<dim3(2048 / 64, 2048 / 256), 256, 0, s2>>>(-1, target_span, -1, span_W1, 1, nullptr, 2048, 2048, 2048);
    bias_act_k<<<(BATCH * 2048 + 255) / 256, 256, 0, s2>>>(1, span_b1, 2048, 1);
    sgemm_k<false><<<dim3(D / 64, 2048 / 256), 256, 0, s2>>>(1, nullptr, -1, span_W2, 2, nullptr, 2048, D, D);
    bias_act_k<<<(BATCH * D + 255) / 256, 256, 0, s2>>>(2, span_b2, D, 0);
    sgemm_k<false><<<dim3(D / 64, D / 256), 256, 0, s2>>>(2, nullptr, -1, fp_W1, 3, nullptr, D, D, D);
    bias_act_k<<<(BATCH * D + 255) / 256, 256, 0, s2>>>(3, fp_b1, D, 1);
    sgemm_k<false><<<dim3(D / 64, D / 256), 256, 0, s2>>>(3, nullptr, -1, fp_W2, 4, nullptr, D, D, D);
    bias_act_k<<<(BATCH * D + 255) / 256, 256, 0, s2>>>(4, fp_b2, D, 2);
    cudaEventRecord(ev2, s2);

    // join s1 before the GNN pipeline
    cudaStreamWaitEvent(0, ev1, 0);

    // Layer 1 (full M, pure tf32)
    spmm1_k<<<NSEG, 128>>>();
    gemm1_k<<<dim3(D / 128, (N_NODES + 63) / 64), 128, G1_SMEM>>>();
    // Layer 2 (M truncated to FRAME, bf16x3 fully corrected, split-K=5)
    spmm2_k<<<N_REL * FRAME, 128>>>();
    gemm2_k<<<dim3(M2PAD / 64, D / 128, KSL), 128, G2_SMEM>>>();
    finalize_k<<<(FRAME * D + 255) / 256, 256>>>();

    // join s2, then einsum + gather
    cudaStreamWaitEvent(0, ev2, 0);
    sgemm_k<true><<<dim3((FRAME + 63) / 64, D / 256), 256>>>(4, nullptr, 5, nullptr, -1, out, D, FRAME, OUTW);
    fgather_k<<<BATCH, 128>>>(gold, flist, out);
}